// round 10
// baseline (speedup 1.0000x reference)
#include <cuda_runtime.h>
#include <cstdint>

// Problem constants
#define BB 16
#define NN 12800
#define FM 128          // F_MSG
#define FN 256          // F_NODE
#define NBINS 100       // N / BIN_SIZE
#define HB 50           // NBINS / 2
#define BS 128          // BIN_SIZE
#define NKEYS 200       // bin keys in [0, 198]
#define ROTC 100        // rot second-dim stride (MAX_NUM_BINS/2)

// Output layout (flattened float32, reference tuple order)
#define OFF_BINS   0
#define LEN_BINS   (BB * NN)                  // 204800
#define OFF_XNODE  (OFF_BINS + LEN_BINS)      // 204800
#define LEN_XNODE  (BB * NN * FN)             // 52428800
#define OFF_DM     (OFF_XNODE + LEN_XNODE)    // 52633600
#define LEN_DM     (BB * NN * BS)             // 26214400
#define OFF_MSKF   (OFF_DM + LEN_DM)          // 78848000

// Scratch (device globals: no allocation allowed)
__device__ int g_key[BB * NN];    // bin key per (b,n)
__device__ int g_bins[BB * NN];   // sorted original indices (bins_split)

typedef unsigned long long u64;

__device__ __forceinline__ float ex2f(float x) {
    float y; asm("ex2.approx.f32 %0, %1;" : "=f"(y) : "f"(x)); return y;
}
__device__ __forceinline__ float rsqf(float x) {
    float y; asm("rsqrt.approx.f32 %0, %1;" : "=f"(y) : "f"(x)); return y;
}
// packed fp32x2 helpers (bit-exact per-lane IEEE fp32 FMA)
__device__ __forceinline__ u64 pack2(float x, float y) {
    u64 r; asm("mov.b64 %0, {%1, %2};" : "=l"(r) : "f"(x), "f"(y)); return r;
}
__device__ __forceinline__ void unpack2(u64 v, float& x, float& y) {
    asm("mov.b64 {%0, %1}, %2;" : "=f"(x), "=f"(y) : "l"(v));
}
__device__ __forceinline__ void fma2(u64& d, u64 a, u64 b) {
    asm("fma.rn.f32x2 %0, %1, %2, %0;" : "+l"(d) : "l"(a), "l"(b));
}

// ---------------------------------------------------------------------------
// K1: LSH projection + argmax -> bin key.  Register-tiled GEMM.
// v4: 256 threads/block, thread tile 4 nodes x 8 h (was 8x8/128thr).
// Same per-(node,h) f-ascending accumulation order -> bit-identical keys.
// Fewer regs (acc 16 u64, av 4 float4) -> occ 3 blocks x 8 warps = 24 w/SM.
// ---------------------------------------------------------------------------
__global__ void __launch_bounds__(256, 3)
k_proj(const float* __restrict__ x_msg,
       const int* __restrict__ msk,
       const float* __restrict__ rot) {
    const int b  = blockIdx.x / (NN / 128);
    const int n0 = (blockIdx.x % (NN / 128)) * 128;
    __shared__ float Rs[128 * 64];
    const int tid = threadIdx.x;     // 256
    const int jx = tid & 7;          // h-group 0..7
    const int iy = tid >> 3;         // node-group 0..31 (4 nodes each)

    // stage Rs (rot is tiny & L2-resident; scattered reads OK)
    for (int idx = tid; idx < 128 * 64; idx += 256) {
        int f = idx >> 6, hp = idx & 63;
        int half = hp >> 5;
        int g    = (hp & 31) >> 2;
        int e    = (hp & 3) + half * 4;
        int h    = g * 8 + e;
        Rs[idx] = (h < HB) ? rot[f * ROTC + h] : 0.f;
    }
    __syncthreads();

    u64 acc[4][4];
#pragma unroll
    for (int k = 0; k < 4; k++)
#pragma unroll
        for (int p = 0; p < 4; p++) acc[k][p] = pack2(0.f, 0.f);

    const float4* xb4 = (const float4*)(x_msg + ((size_t)b * NN + n0) * FM);
    for (int f4 = 0; f4 < FM / 4; f4++) {
        float4 av[4];
#pragma unroll
        for (int k = 0; k < 4; k++)
            av[k] = xb4[(size_t)(iy * 4 + k) * (FM / 4) + f4];
#pragma unroll
        for (int ff = 0; ff < 4; ff++) {
            const float* rrow = Rs + (f4 * 4 + ff) * 64;
            ulonglong2 q0 = *(const ulonglong2*)(rrow + jx * 4);
            ulonglong2 q1 = *(const ulonglong2*)(rrow + 32 + jx * 4);
#pragma unroll
            for (int k = 0; k < 4; k++) {
                float a = (ff == 0) ? av[k].x : (ff == 1) ? av[k].y
                         : (ff == 2) ? av[k].z : av[k].w;
                u64 a2 = pack2(a, a);
                fma2(acc[k][0], a2, q0.x);
                fma2(acc[k][1], a2, q0.y);
                fma2(acc[k][2], a2, q1.x);
                fma2(acc[k][3], a2, q1.y);
            }
        }
    }

    // per-node argmax/argmin over 64 h (8 local + shuffle over 8 jx lanes)
#pragma unroll
    for (int k = 0; k < 4; k++) {
        float v[8];
#pragma unroll
        for (int p = 0; p < 4; p++) unpack2(acc[k][p], v[2 * p], v[2 * p + 1]);
        float bv = v[0]; int bh = jx * 8;
        float mv = v[0]; int mh = jx * 8;
#pragma unroll
        for (int e = 1; e < 8; e++) {
            int h = jx * 8 + e;
            if (v[e] > bv) { bv = v[e]; bh = h; }
            if (v[e] < mv) { mv = v[e]; mh = h; }
        }
#pragma unroll
        for (int off = 1; off < 8; off <<= 1) {
            float obv = __shfl_xor_sync(0xffffffffu, bv, off);
            int   obh = __shfl_xor_sync(0xffffffffu, bh, off);
            float omv = __shfl_xor_sync(0xffffffffu, mv, off);
            int   omh = __shfl_xor_sync(0xffffffffu, mh, off);
            if (obv > bv || (obv == bv && obh < bh)) { bv = obv; bh = obh; }
            if (omv < mv || (omv == mv && omh < mh)) { mv = omv; mh = omh; }
        }
        if (jx == 0) {
            int idx = (bv >= -mv) ? bh : (HB + mh);
            int n = n0 + iy * 4 + k;
            int m = msk[(size_t)b * NN + n];
            g_key[(size_t)b * NN + n] = idx + (m ? 0 : (NBINS - 1));
        }
    }
}

// ---------------------------------------------------------------------------
// K2: stable counting sort per batch (unchanged).
// ---------------------------------------------------------------------------
__global__ void k_sort(const int* __restrict__ msk,
                       float* __restrict__ out) {
    const int b = blockIdx.x;
    extern __shared__ unsigned short off[];        // [NKEYS][128]
    __shared__ unsigned int keyTotal[NKEYS];
    __shared__ unsigned int keyBase[NKEYS];
    const int t = threadIdx.x;

    for (int i = t; i < NKEYS * 128; i += 128) off[i] = 0;
    __syncthreads();

    const int* kb = g_key + (size_t)b * NN;
    const int base_n = t * 100;
    for (int q = 0; q < 100; q++) {
        int k = kb[base_n + q];
        off[k * 128 + t]++;
    }
    __syncthreads();

    for (int k = t; k < NKEYS; k += 128) {
        unsigned int run = 0;
        for (int tt = 0; tt < 128; tt++) {
            unsigned short c = off[k * 128 + tt];
            off[k * 128 + tt] = (unsigned short)run;
            run += c;
        }
        keyTotal[k] = run;
    }
    __syncthreads();
    if (t == 0) {
        unsigned int run = 0;
        for (int k = 0; k < NKEYS; k++) { keyBase[k] = run; run += keyTotal[k]; }
    }
    __syncthreads();

    int* gb = g_bins + (size_t)b * NN;
    const int* mb = msk + (size_t)b * NN;
    float* out_bins = out + OFF_BINS + (size_t)b * NN;
    float* out_mskf = out + OFF_MSKF + (size_t)b * NN;
    for (int q = 0; q < 100; q++) {
        int n = base_n + q;
        int k = kb[n];
        unsigned int pos = keyBase[k] + off[k * 128 + t];
        off[k * 128 + t]++;
        gb[pos] = n;
        out_bins[pos] = (float)n;
        out_mskf[pos] = mb[n] ? 1.0f : 0.0f;
    }
}

// ---------------------------------------------------------------------------
// K4: per-bin pairwise gaussian kernel + fused x_node gather. (unchanged)
// 512 threads; conflict-free staging; 272 8x4 half-tiles; mirror writes;
// warps 9-15 overlap the x_node gather.
// ---------------------------------------------------------------------------
#define ST 132
__global__ void __launch_bounds__(512, 2)
k_dm(const float4* __restrict__ x_msg4,
     const int* __restrict__ msk,
     const float4* __restrict__ x_node4,
     float* __restrict__ out) {
    const int b   = blockIdx.x / NBINS;
    const int bin = blockIdx.x % NBINS;
    extern __shared__ float sm4[];
    float* As  = sm4;                    // [128][ST], f-major (A transposed)
    float* na  = sm4 + 128 * ST;         // [128]
    float* mm  = na + 128;               // [128]
    float* nap = mm + 128;               // [4][128] na partials
    const int tid  = threadIdx.x;        // 512
    const int w    = tid >> 5;           // 0..15
    const int lane = tid & 31;

    const int* gb = g_bins + ((size_t)b * NBINS + bin) * BS;
    const float4* xb = x_msg4 + (size_t)b * NN * (FM / 4);

    // Conflict-free staging: fgroup fg handles f4 in [fg*8, fg*8+8).
    {
        const int fg = w >> 2;           // 0..3
        const int rb = w & 3;            // 0..3
        const int r  = rb * 32 + lane;   // row owned by this lane
        const int src = gb[r];
        const float m = msk[(size_t)b * NN + src] ? 1.f : 0.f;
        const float4* xrow = xb + (size_t)src * (FM / 4);
        float s = 0.f;
#pragma unroll
        for (int k = 0; k < 8; k++) {
            const int f4 = fg * 8 + k;
            float4 v = xrow[f4];
            v.x *= m; v.y *= m; v.z *= m; v.w *= m;
            As[(4 * f4 + 0) * ST + r] = v.x;
            As[(4 * f4 + 1) * ST + r] = v.y;
            As[(4 * f4 + 2) * ST + r] = v.z;
            As[(4 * f4 + 3) * ST + r] = v.w;
            s += v.x * v.x + v.y * v.y + v.z * v.z + v.w * v.w;
        }
        nap[fg * 128 + r] = s;
        if (fg == 0) mm[r] = m;
    }
    __syncthreads();
    if (tid < 128) {
        na[tid] = (nap[tid] + nap[128 + tid]) + (nap[256 + tid] + nap[384 + tid]);
    }
    __syncthreads();

    if (tid < 272) {
        const int tile = tid >> 1;
        const int half = tid & 1;
        // map tile -> (ty, tx) in upper triangle (tx >= ty) of 16x16 grid
        int ty = 0, rem = tile;
        while (rem >= 16 - ty) { rem -= 16 - ty; ty++; }
        const int tx = ty + rem;
        const int i0 = ty * 8;
        const int j0 = tx * 8 + half * 4;   // 4-col half

        u64 acc2[8][2];
#pragma unroll
        for (int u = 0; u < 8; u++) {
            acc2[u][0] = pack2(0.f, 0.f);
            acc2[u][1] = pack2(0.f, 0.f);
        }

        for (int f = 0; f < FM; f++) {
            const float* row = As + f * ST;
            float4 a0 = *(const float4*)(row + i0);
            float4 a1 = *(const float4*)(row + i0 + 4);
            ulonglong2 q = *(const ulonglong2*)(row + j0);   // (c0,c1),(c2,c3)
            float a[8] = {a0.x, a0.y, a0.z, a0.w, a1.x, a1.y, a1.z, a1.w};
#pragma unroll
            for (int u = 0; u < 8; u++) {
                u64 au = pack2(a[u], a[u]);
                fma2(acc2[u][0], au, q.x);
                fma2(acc2[u][1], au, q.y);
            }
        }

        float* dout = out + OFF_DM + (size_t)blockIdx.x * BS * BS;
        const float c = -0.14426950408889634f;   // -DIST_MULT * log2(e)
        float res[8][4];
#pragma unroll
        for (int u = 0; u < 8; u++) {
            float g[4];
            unpack2(acc2[u][0], g[0], g[1]);
            unpack2(acc2[u][1], g[2], g[3]);
            const float nai = na[i0 + u];
            const float mi  = mm[i0 + u];
#pragma unroll
            for (int v = 0; v < 4; v++) {
                float x = fmaxf(nai + na[j0 + v] - 2.0f * g[v], 1e-6f);
                float d = x * rsqf(x);            // sqrt(x), x >= 1e-6
                float val = ex2f(c * d) * mi * mm[j0 + v];
                res[u][v] = fminf(val, 1.0f);
            }
            *(float4*)(dout + (size_t)(i0 + u) * BS + j0) =
                make_float4(res[u][0], res[u][1], res[u][2], res[u][3]);
        }
        // mirrored 4x8 block at (j0.., i0..) — dm is exactly symmetric
        if (tx != ty) {
#pragma unroll
            for (int v = 0; v < 4; v++) {
                float4* p = (float4*)(dout + (size_t)(j0 + v) * BS + i0);
                p[0] = make_float4(res[0][v], res[1][v], res[2][v], res[3][v]);
                p[1] = make_float4(res[4][v], res[5][v], res[6][v], res[7][v]);
            }
        }
    }

    // Fused x_node gather: 128 rows of 256 floats (64 float4 each).
    // Warps 9-15 reach here right after the na barrier (overlap with gram).
    const float4* xn = x_node4 + (size_t)b * NN * (FN / 4);
    float4* xo = (float4*)(out + OFF_XNODE) + (size_t)blockIdx.x * BS * (FN / 4);
    for (int r = w; r < BS; r += 16) {
        int src = gb[r];
        const float4* s = xn + (size_t)src * (FN / 4);
        float4* d = xo + (size_t)r * (FN / 4);
#pragma unroll
        for (int c4 = 0; c4 < 2; c4++) d[lane + 32 * c4] = s[lane + 32 * c4];
    }
}

// ---------------------------------------------------------------------------
extern "C" void kernel_launch(void* const* d_in, const int* in_sizes, int n_in,
                              void* d_out, int out_size) {
    const float* x_msg  = (const float*)d_in[0];
    const float* x_node = (const float*)d_in[1];
    const int*   msk    = (const int*)d_in[2];
    const float* rot    = (const float*)d_in[3];
    float* out = (float*)d_out;

    const int SM2 = NKEYS * 128 * 2;                         // 51200
    const int SM4 = 128 * ST * 4 + (128 + 128 + 512) * 4;    // 70656
    cudaFuncSetAttribute(k_sort, cudaFuncAttributeMaxDynamicSharedMemorySize, SM2);
    cudaFuncSetAttribute(k_dm,   cudaFuncAttributeMaxDynamicSharedMemorySize, SM4);

    k_proj<<<BB * (NN / 128), 256>>>(x_msg, msk, rot);
    k_sort<<<BB, 128, SM2>>>(msk, out);
    k_dm<<<BB * NBINS, 512, SM4>>>((const float4*)x_msg, msk,
                                   (const float4*)x_node, out);
}

// round 11
// speedup vs baseline: 1.0033x; 1.0033x over previous
#include <cuda_runtime.h>
#include <cstdint>

// Problem constants
#define BB 16
#define NN 12800
#define FM 128          // F_MSG
#define FN 256          // F_NODE
#define NBINS 100       // N / BIN_SIZE
#define HB 50           // NBINS / 2
#define BS 128          // BIN_SIZE
#define NKEYS 200       // bin keys in [0, 198]
#define ROTC 100        // rot second-dim stride (MAX_NUM_BINS/2)

// Output layout (flattened float32, reference tuple order)
#define OFF_BINS   0
#define LEN_BINS   (BB * NN)                  // 204800
#define OFF_XNODE  (OFF_BINS + LEN_BINS)      // 204800
#define LEN_XNODE  (BB * NN * FN)             // 52428800
#define OFF_DM     (OFF_XNODE + LEN_XNODE)    // 52633600
#define LEN_DM     (BB * NN * BS)             // 26214400
#define OFF_MSKF   (OFF_DM + LEN_DM)          // 78848000

// Scratch (device globals: no allocation allowed)
__device__ int g_key[BB * NN];    // bin key per (b,n)
__device__ int g_bins[BB * NN];   // sorted original indices (bins_split)

typedef unsigned long long u64;

__device__ __forceinline__ float ex2f(float x) {
    float y; asm("ex2.approx.f32 %0, %1;" : "=f"(y) : "f"(x)); return y;
}
__device__ __forceinline__ float rsqf(float x) {
    float y; asm("rsqrt.approx.f32 %0, %1;" : "=f"(y) : "f"(x)); return y;
}
// packed fp32x2 helpers (bit-exact per-lane IEEE fp32 FMA)
__device__ __forceinline__ u64 pack2(float x, float y) {
    u64 r; asm("mov.b64 %0, {%1, %2};" : "=l"(r) : "f"(x), "f"(y)); return r;
}
__device__ __forceinline__ void unpack2(u64 v, float& x, float& y) {
    asm("mov.b64 {%0, %1}, %2;" : "=f"(x), "=f"(y) : "l"(v));
}
__device__ __forceinline__ void fma2(u64& d, u64 a, u64 b) {
    asm("fma.rn.f32x2 %0, %1, %2, %0;" : "+l"(d) : "l"(a), "l"(b));
}

// ---------------------------------------------------------------------------
// K1: LSH projection + argmax -> bin key.  Register-tiled GEMM. (unchanged;
// at combined L1+FMA floor ~88us; occupancy changes proven neutral R9/R10)
// ---------------------------------------------------------------------------
__global__ void __launch_bounds__(256, 3)
k_proj(const float* __restrict__ x_msg,
       const int* __restrict__ msk,
       const float* __restrict__ rot) {
    const int b  = blockIdx.x / (NN / 128);
    const int n0 = (blockIdx.x % (NN / 128)) * 128;
    __shared__ float Rs[128 * 64];
    const int tid = threadIdx.x;     // 256
    const int jx = tid & 7;          // h-group 0..7
    const int iy = tid >> 3;         // node-group 0..31 (4 nodes each)

    for (int idx = tid; idx < 128 * 64; idx += 256) {
        int f = idx >> 6, hp = idx & 63;
        int half = hp >> 5;
        int g    = (hp & 31) >> 2;
        int e    = (hp & 3) + half * 4;
        int h    = g * 8 + e;
        Rs[idx] = (h < HB) ? rot[f * ROTC + h] : 0.f;
    }
    __syncthreads();

    u64 acc[4][4];
#pragma unroll
    for (int k = 0; k < 4; k++)
#pragma unroll
        for (int p = 0; p < 4; p++) acc[k][p] = pack2(0.f, 0.f);

    const float4* xb4 = (const float4*)(x_msg + ((size_t)b * NN + n0) * FM);
    for (int f4 = 0; f4 < FM / 4; f4++) {
        float4 av[4];
#pragma unroll
        for (int k = 0; k < 4; k++)
            av[k] = xb4[(size_t)(iy * 4 + k) * (FM / 4) + f4];
#pragma unroll
        for (int ff = 0; ff < 4; ff++) {
            const float* rrow = Rs + (f4 * 4 + ff) * 64;
            ulonglong2 q0 = *(const ulonglong2*)(rrow + jx * 4);
            ulonglong2 q1 = *(const ulonglong2*)(rrow + 32 + jx * 4);
#pragma unroll
            for (int k = 0; k < 4; k++) {
                float a = (ff == 0) ? av[k].x : (ff == 1) ? av[k].y
                         : (ff == 2) ? av[k].z : av[k].w;
                u64 a2 = pack2(a, a);
                fma2(acc[k][0], a2, q0.x);
                fma2(acc[k][1], a2, q0.y);
                fma2(acc[k][2], a2, q1.x);
                fma2(acc[k][3], a2, q1.y);
            }
        }
    }

#pragma unroll
    for (int k = 0; k < 4; k++) {
        float v[8];
#pragma unroll
        for (int p = 0; p < 4; p++) unpack2(acc[k][p], v[2 * p], v[2 * p + 1]);
        float bv = v[0]; int bh = jx * 8;
        float mv = v[0]; int mh = jx * 8;
#pragma unroll
        for (int e = 1; e < 8; e++) {
            int h = jx * 8 + e;
            if (v[e] > bv) { bv = v[e]; bh = h; }
            if (v[e] < mv) { mv = v[e]; mh = h; }
        }
#pragma unroll
        for (int off = 1; off < 8; off <<= 1) {
            float obv = __shfl_xor_sync(0xffffffffu, bv, off);
            int   obh = __shfl_xor_sync(0xffffffffu, bh, off);
            float omv = __shfl_xor_sync(0xffffffffu, mv, off);
            int   omh = __shfl_xor_sync(0xffffffffu, mh, off);
            if (obv > bv || (obv == bv && obh < bh)) { bv = obv; bh = obh; }
            if (omv < mv || (omv == mv && omh < mh)) { mv = omv; mh = omh; }
        }
        if (jx == 0) {
            int idx = (bv >= -mv) ? bh : (HB + mh);
            int n = n0 + iy * 4 + k;
            int m = msk[(size_t)b * NN + n];
            g_key[(size_t)b * NN + n] = idx + (m ? 0 : (NBINS - 1));
        }
    }
}

// ---------------------------------------------------------------------------
// K2: stable counting sort per batch (unchanged).
// ---------------------------------------------------------------------------
__global__ void k_sort(const int* __restrict__ msk,
                       float* __restrict__ out) {
    const int b = blockIdx.x;
    extern __shared__ unsigned short off[];        // [NKEYS][128]
    __shared__ unsigned int keyTotal[NKEYS];
    __shared__ unsigned int keyBase[NKEYS];
    const int t = threadIdx.x;

    for (int i = t; i < NKEYS * 128; i += 128) off[i] = 0;
    __syncthreads();

    const int* kb = g_key + (size_t)b * NN;
    const int base_n = t * 100;
    for (int q = 0; q < 100; q++) {
        int k = kb[base_n + q];
        off[k * 128 + t]++;
    }
    __syncthreads();

    for (int k = t; k < NKEYS; k += 128) {
        unsigned int run = 0;
        for (int tt = 0; tt < 128; tt++) {
            unsigned short c = off[k * 128 + tt];
            off[k * 128 + tt] = (unsigned short)run;
            run += c;
        }
        keyTotal[k] = run;
    }
    __syncthreads();
    if (t == 0) {
        unsigned int run = 0;
        for (int k = 0; k < NKEYS; k++) { keyBase[k] = run; run += keyTotal[k]; }
    }
    __syncthreads();

    int* gb = g_bins + (size_t)b * NN;
    const int* mb = msk + (size_t)b * NN;
    float* out_bins = out + OFF_BINS + (size_t)b * NN;
    float* out_mskf = out + OFF_MSKF + (size_t)b * NN;
    for (int q = 0; q < 100; q++) {
        int n = base_n + q;
        int k = kb[n];
        unsigned int pos = keyBase[k] + off[k * 128 + t];
        off[k * 128 + t]++;
        gb[pos] = n;
        out_bins[pos] = (float)n;
        out_mskf[pos] = mb[n] ? 1.0f : 0.0f;
    }
}

// ---------------------------------------------------------------------------
// K4: per-bin pairwise gaussian kernel + fused x_node gather.
// 512 threads, warp-specialized: gram (272 8x4 half-tiles) on warps 0-8;
// the ENTIRE x_node gather on warps 9-15 (stride 7) so it runs fully
// concurrent with the gram loop. Conflict-free staging on all 16 warps.
// ---------------------------------------------------------------------------
#define ST 132
__global__ void __launch_bounds__(512, 2)
k_dm(const float4* __restrict__ x_msg4,
     const int* __restrict__ msk,
     const float4* __restrict__ x_node4,
     float* __restrict__ out) {
    const int b   = blockIdx.x / NBINS;
    const int bin = blockIdx.x % NBINS;
    extern __shared__ float sm4[];
    float* As  = sm4;                    // [128][ST], f-major (A transposed)
    float* na  = sm4 + 128 * ST;         // [128]
    float* mm  = na + 128;               // [128]
    float* nap = mm + 128;               // [4][128] na partials
    const int tid  = threadIdx.x;        // 512
    const int w    = tid >> 5;           // 0..15
    const int lane = tid & 31;

    const int* gb = g_bins + ((size_t)b * NBINS + bin) * BS;
    const float4* xb = x_msg4 + (size_t)b * NN * (FM / 4);

    // Conflict-free staging: fgroup fg handles f4 in [fg*8, fg*8+8).
    {
        const int fg = w >> 2;           // 0..3
        const int rb = w & 3;            // 0..3
        const int r  = rb * 32 + lane;   // row owned by this lane
        const int src = gb[r];
        const float m = msk[(size_t)b * NN + src] ? 1.f : 0.f;
        const float4* xrow = xb + (size_t)src * (FM / 4);
        float s = 0.f;
#pragma unroll
        for (int k = 0; k < 8; k++) {
            const int f4 = fg * 8 + k;
            float4 v = xrow[f4];
            v.x *= m; v.y *= m; v.z *= m; v.w *= m;
            As[(4 * f4 + 0) * ST + r] = v.x;
            As[(4 * f4 + 1) * ST + r] = v.y;
            As[(4 * f4 + 2) * ST + r] = v.z;
            As[(4 * f4 + 3) * ST + r] = v.w;
            s += v.x * v.x + v.y * v.y + v.z * v.z + v.w * v.w;
        }
        nap[fg * 128 + r] = s;
        if (fg == 0) mm[r] = m;
    }
    __syncthreads();
    if (tid < 128) {
        na[tid] = (nap[tid] + nap[128 + tid]) + (nap[256 + tid] + nap[384 + tid]);
    }
    __syncthreads();

    if (w >= 9) {
        // Gather warps: copy this bin's 128 x_node rows (256 floats each),
        // fully overlapped with the gram loop on warps 0-8.
        const float4* xn = x_node4 + (size_t)b * NN * (FN / 4);
        float4* xo = (float4*)(out + OFF_XNODE) + (size_t)blockIdx.x * BS * (FN / 4);
        for (int r = w - 9; r < BS; r += 7) {
            int src = gb[r];
            const float4* s = xn + (size_t)src * (FN / 4);
            float4* d = xo + (size_t)r * (FN / 4);
#pragma unroll
            for (int c4 = 0; c4 < 2; c4++) d[lane + 32 * c4] = s[lane + 32 * c4];
        }
        return;
    }

    if (tid < 272) {
        const int tile = tid >> 1;
        const int half = tid & 1;
        // map tile -> (ty, tx) in upper triangle (tx >= ty) of 16x16 grid
        int ty = 0, rem = tile;
        while (rem >= 16 - ty) { rem -= 16 - ty; ty++; }
        const int tx = ty + rem;
        const int i0 = ty * 8;
        const int j0 = tx * 8 + half * 4;   // 4-col half

        u64 acc2[8][2];
#pragma unroll
        for (int u = 0; u < 8; u++) {
            acc2[u][0] = pack2(0.f, 0.f);
            acc2[u][1] = pack2(0.f, 0.f);
        }

        for (int f = 0; f < FM; f++) {
            const float* row = As + f * ST;
            float4 a0 = *(const float4*)(row + i0);
            float4 a1 = *(const float4*)(row + i0 + 4);
            ulonglong2 q = *(const ulonglong2*)(row + j0);   // (c0,c1),(c2,c3)
            float a[8] = {a0.x, a0.y, a0.z, a0.w, a1.x, a1.y, a1.z, a1.w};
#pragma unroll
            for (int u = 0; u < 8; u++) {
                u64 au = pack2(a[u], a[u]);
                fma2(acc2[u][0], au, q.x);
                fma2(acc2[u][1], au, q.y);
            }
        }

        float* dout = out + OFF_DM + (size_t)blockIdx.x * BS * BS;
        const float c = -0.14426950408889634f;   // -DIST_MULT * log2(e)
        float res[8][4];
#pragma unroll
        for (int u = 0; u < 8; u++) {
            float g[4];
            unpack2(acc2[u][0], g[0], g[1]);
            unpack2(acc2[u][1], g[2], g[3]);
            const float nai = na[i0 + u];
            const float mi  = mm[i0 + u];
#pragma unroll
            for (int v = 0; v < 4; v++) {
                float x = fmaxf(nai + na[j0 + v] - 2.0f * g[v], 1e-6f);
                float d = x * rsqf(x);            // sqrt(x), x >= 1e-6
                float val = ex2f(c * d) * mi * mm[j0 + v];
                res[u][v] = fminf(val, 1.0f);
            }
            *(float4*)(dout + (size_t)(i0 + u) * BS + j0) =
                make_float4(res[u][0], res[u][1], res[u][2], res[u][3]);
        }
        // mirrored 4x8 block at (j0.., i0..) — dm is exactly symmetric
        if (tx != ty) {
#pragma unroll
            for (int v = 0; v < 4; v++) {
                float4* p = (float4*)(dout + (size_t)(j0 + v) * BS + i0);
                p[0] = make_float4(res[0][v], res[1][v], res[2][v], res[3][v]);
                p[1] = make_float4(res[4][v], res[5][v], res[6][v], res[7][v]);
            }
        }
    }
}

// ---------------------------------------------------------------------------
extern "C" void kernel_launch(void* const* d_in, const int* in_sizes, int n_in,
                              void* d_out, int out_size) {
    const float* x_msg  = (const float*)d_in[0];
    const float* x_node = (const float*)d_in[1];
    const int*   msk    = (const int*)d_in[2];
    const float* rot    = (const float*)d_in[3];
    float* out = (float*)d_out;

    const int SM2 = NKEYS * 128 * 2;                         // 51200
    const int SM4 = 128 * ST * 4 + (128 + 128 + 512) * 4;    // 70656
    cudaFuncSetAttribute(k_sort, cudaFuncAttributeMaxDynamicSharedMemorySize, SM2);
    cudaFuncSetAttribute(k_dm,   cudaFuncAttributeMaxDynamicSharedMemorySize, SM4);

    k_proj<<<BB * (NN / 128), 256>>>(x_msg, msk, rot);
    k_sort<<<BB, 128, SM2>>>(msk, out);
    k_dm<<<BB * NBINS, 512, SM4>>>((const float4*)x_msg, msk,
                                   (const float4*)x_node, out);
}